// round 4
// baseline (speedup 1.0000x reference)
#include <cuda_runtime.h>
#include <math.h>

// Batched EKF, decomposed into three independent 2x2 filters per segment
// (blocks {0,2},{1,3},{4,5}).  One thread per segment (ILP=3 inside the
// thread -- this beat the 3-thread split).  Blocks A and B run identical
// code -> packed f32x2 (FFMA2) arithmetic.  lg2 batched per 4 steps.
// Depth-2 float4 prefetch of measurements.  Fused deterministic reduction.

#define THREADS 32

__device__ float g_partials[512];
__device__ int   g_count = 0;

typedef unsigned long long u64;

__device__ __forceinline__ float tanh_fast(float x){ float y; asm("tanh.approx.f32 %0, %1;" : "=f"(y) : "f"(x)); return y; }
__device__ __forceinline__ float rcp_fast (float x){ float y; asm("rcp.approx.f32 %0, %1;"  : "=f"(y) : "f"(x)); return y; }
__device__ __forceinline__ float lg2_fast (float x){ float y; asm("lg2.approx.f32 %0, %1;"  : "=f"(y) : "f"(x)); return y; }

__device__ __forceinline__ u64 pk(float lo, float hi){ u64 r; asm("mov.b64 %0, {%1, %2};" : "=l"(r) : "f"(lo), "f"(hi)); return r; }
__device__ __forceinline__ void upk(u64 v, float& lo, float& hi){ asm("mov.b64 {%0, %1}, %2;" : "=f"(lo), "=f"(hi) : "l"(v)); }
__device__ __forceinline__ u64 fma2(u64 a, u64 b, u64 c){ u64 r; asm("fma.rn.f32x2 %0, %1, %2, %3;" : "=l"(r) : "l"(a), "l"(b), "l"(c)); return r; }
__device__ __forceinline__ u64 mul2(u64 a, u64 b){ u64 r; asm("mul.rn.f32x2 %0, %1, %2;" : "=l"(r) : "l"(a), "l"(b)); return r; }
__device__ __forceinline__ u64 add2(u64 a, u64 b){ u64 r; asm("add.rn.f32x2 %0, %1, %2;" : "=l"(r) : "l"(a), "l"(b)); return r; }

__global__ void __launch_bounds__(THREADS) ekf_kernel(
    const float* __restrict__ params,
    const float* __restrict__ cp,
    const float* __restrict__ init_state,
    const float* __restrict__ meas,
    float* __restrict__ out,
    int N, int T)
{
    const float DT    = 1.0f / 120.0f;
    const float GRAV  = 9.81f;
    const float KS    = 100.0f;
    const float WRAP  = 4.71238898038469f;   // 1.5*pi
    const float TWOPI = 6.283185307179586f;
    const float LN2   = 0.6931471805599453f;

    const float fric = fabsf(params[0]);
    const float damp = fabsf(params[1]);
    const float R0 = expf(cp[0]);
    const float R1 = expf(cp[1]);
    const float R2v= expf(cp[2]);
    const float Qp = expf(cp[3]);
    const float Qv = expf(cp[4]);
    const float Qt = expf(cp[5]);
    const float Qo = expf(cp[6]);

    const float fg    = fric * GRAV;
    const float cF    = 1.0f - DT * damp;
    const float DTfgk = DT * fg * KS;
    const float cF2s  = cF * cF;

    // packed constants (both lanes equal unless noted)
    const u64 cDT    = pk(DT, DT);
    const u64 cNDT   = pk(-DT, -DT);
    const u64 cKS    = pk(KS, KS);
    const u64 cFG    = pk(fg, fg);
    const u64 cDAMP  = pk(damp, damp);
    const u64 cDTFGK = pk(DTfgk, DTfgk);
    const u64 cCF    = pk(cF, cF);
    const u64 cQp    = pk(Qp, Qp);
    const u64 cQv    = pk(Qv, Qv);
    const u64 cR     = pk(R0, R1);            // per-lane R!
    const u64 cNEG1  = pk(-1.0f, -1.0f);
    const u64 cONE   = pk(1.0f, 1.0f);

    int n = blockIdx.x * THREADS + threadIdx.x;

    float acc_l2 = 0.0f;
    float acc_mC = 0.0f;
    u64   accm2  = pk(0.0f, 0.0f);

    if (n < N) {
        // packed state: lane0 = block A {x0,x2}, lane1 = block B {x1,x3}
        u64 x2v = pk(init_state[n*6+0], init_state[n*6+1]);
        u64 v2v = pk(init_state[n*6+2], init_state[n*6+3]);
        float xC = init_state[n*6+4], vC = init_state[n*6+5];

        u64 p00_2 = pk(0.01f, 0.01f), p01_2 = pk(0.0f, 0.0f), p11_2 = pk(0.01f, 0.01f);
        float pC00 = 0.01f, pC01 = 0.0f, pC11 = 0.01f;

        const float*  mp  = meas + (size_t)n * T * 3;
        const float4* mp4 = (const float4*)mp;

#define STEP(z0_, z1_, z2_) do {                                               \
        u64 z2p = pk((z0_), (z1_));                                            \
        /* ---- packed A/B ---- */                                             \
        float va_, vb_;  upk(mul2(v2v, cKS), va_, vb_);                        \
        u64 t2 = pk(tanh_fast(va_), tanh_fast(vb_));                           \
        u64 xp2 = fma2(cDT, v2v, x2v);                                         \
        u64 vp2 = fma2(cNDT, fma2(cFG, t2, mul2(cDAMP, v2v)), v2v);           \
        u64 a2  = fma2(cDTFGK, fma2(t2, t2, cNEG1), cCF);                      \
        u64 q2  = fma2(cDT, p11_2, add2(p01_2, p01_2));                        \
        u64 Pp00 = add2(fma2(cDT, q2, p00_2), cQp);                            \
        u64 Pp01 = mul2(a2, fma2(cDT, p11_2, p01_2));                          \
        u64 Pp11 = fma2(mul2(a2, a2), p11_2, cQv);                             \
        u64 y2v = fma2(xp2, cNEG1, z2p);                                       \
        u64 S2  = add2(Pp00, cR);                                              \
        float sa_, sb_;  upk(S2, sa_, sb_);                                    \
        u64 iS2 = pk(rcp_fast(sa_), rcp_fast(sb_));                            \
        u64 k0 = mul2(Pp00, iS2);                                              \
        u64 k1 = mul2(Pp01, iS2);                                              \
        x2v = fma2(k0, y2v, xp2);                                              \
        v2v = fma2(k1, y2v, vp2);                                              \
        u64 om2 = fma2(k0, cNEG1, cONE);                                       \
        p00_2 = mul2(Pp00, om2);                                               \
        p01_2 = mul2(Pp01, om2);                                               \
        p11_2 = fma2(mul2(k1, cNEG1), Pp01, Pp11);                             \
        accm2 = fma2(mul2(y2v, y2v), iS2, accm2);                              \
        sp2   = mul2(sp2, S2);                                                 \
        /* ---- scalar C (linear, angle wrap) ---- */                          \
        {                                                                      \
            float xp  = fmaf(DT, vC, xC);                                      \
            float vp  = cF * vC;                                               \
            float Pq00 = fmaf(DT, fmaf(DT, pC11, pC01 + pC01), pC00) + Qt;     \
            float Pq01 = cF * fmaf(DT, pC11, pC01);                            \
            float Pq11 = fmaf(cF2s, pC11, Qo);                                 \
            float y = (z2_) - xp;                                              \
            if      (y >  WRAP) y -= TWOPI;                                    \
            else if (y < -WRAP) y += TWOPI;                                    \
            float S  = Pq00 + R2v;                                             \
            float iS = rcp_fast(S);                                            \
            float k0c = Pq00 * iS, k1c = Pq01 * iS;                            \
            xC = fmaf(k0c, y, xp);  vC = fmaf(k1c, y, vp);                     \
            float om = 1.0f - k0c;                                             \
            pC00 = Pq00 * om; pC01 = Pq01 * om;                                \
            pC11 = fmaf(-k1c, Pq01, Pq11);                                     \
            acc_mC = fmaf(y * y, iS, acc_mC);                                  \
            spC *= S;                                                          \
        }                                                                      \
    } while (0)

        int G = T >> 2;
        if ((T & 3) == 0 && G >= 2) {
            float4 c0 = mp4[0], c1 = mp4[1], c2 = mp4[2];
            float4 d0 = mp4[3], d1 = mp4[4], d2 = mp4[5];
            for (int g = 0; g < G; g++) {
                float4 e0, e1, e2;
                if (g + 2 < G) {
                    int b = (g + 2) * 3;
                    e0 = mp4[b]; e1 = mp4[b+1]; e2 = mp4[b+2];
                }
                u64 sp2 = pk(1.0f, 1.0f);
                float spC = 1.0f;
                STEP(c0.x, c0.y, c0.z);
                STEP(c0.w, c1.x, c1.y);
                STEP(c1.z, c1.w, c2.x);
                STEP(c2.y, c2.z, c2.w);
                float pa_, pb_;
                upk(sp2, pa_, pb_);
                acc_l2 += lg2_fast(pa_ * pb_ * spC);
                c0 = d0; c1 = d1; c2 = d2;
                d0 = e0; d1 = e1; d2 = e2;
            }
        } else {
            for (int t = 0; t < T; t++) {
                u64 sp2 = pk(1.0f, 1.0f);
                float spC = 1.0f;
                float z0 = mp[t*3+0], z1 = mp[t*3+1], z2 = mp[t*3+2];
                STEP(z0, z1, z2);
                float pa_, pb_;
                upk(sp2, pa_, pb_);
                acc_l2 += lg2_fast(pa_ * pb_ * spC);
            }
        }
#undef STEP
    }

    float mA, mB;
    upk(accm2, mA, mB);
    float loss = 0.5f * fmaf(LN2, acc_l2, (mA + mB) + acc_mC);

    // deterministic warp-tree reduction
    #pragma unroll
    for (int o = 16; o > 0; o >>= 1)
        loss += __shfl_down_sync(0xffffffffu, loss, o);

    int nb = gridDim.x;
    int last = 0;
    if (threadIdx.x == 0) {
        g_partials[blockIdx.x] = loss;
        __threadfence();
        int old = atomicAdd(&g_count, 1);
        last = (old == nb - 1);
    }
    last = __shfl_sync(0xffffffffu, last, 0);
    if (last) {
        __threadfence();
        float s = 0.0f;
        for (int j = (int)threadIdx.x; j < nb; j += 32)
            s += g_partials[j];
        #pragma unroll
        for (int o = 16; o > 0; o >>= 1)
            s += __shfl_down_sync(0xffffffffu, s, o);
        if (threadIdx.x == 0) {
            out[0] = s / (float)N;
            g_count = 0;   // reset for next graph replay
        }
    }
}

extern "C" void kernel_launch(void* const* d_in, const int* in_sizes, int n_in,
                              void* d_out, int out_size)
{
    const float* params = (const float*)d_in[0];
    const float* cp     = (const float*)d_in[1];
    const float* x0     = (const float*)d_in[2];
    const float* meas   = (const float*)d_in[3];
    float* out = (float*)d_out;

    int N = in_sizes[2] / 6;
    int T = in_sizes[3] / (N * 3);
    int nblocks = (N + THREADS - 1) / THREADS;

    ekf_kernel<<<nblocks, THREADS>>>(params, cp, x0, meas, out, N, T);
}